// round 10
// baseline (speedup 1.0000x reference)
#include <cuda_runtime.h>
#include <cstdint>

#define B_DIM 2048
#define N_DIM 512
#define C_DIM 64
#define L_DIM 2
#define O_DIM 8192
#define LO (L_DIM * O_DIM)      // 16384
#define LO4 (LO / 4)            // 4096

#define BPB 4                   // batches per gather block
#define CHUNK 2048              // lo per gather block
#define CHUNK4 (CHUNK / 4)      // 512 int4 per chunk
#define NCHUNK (LO / CHUNK)     // 8

// Selection table sel[l*O + o] = input-feature index (0..N-1)
__device__ int g_sel[LO];

// ---------------------------------------------------------------------------
// Kernel 1: argmax over C=64 candidates per (l,o), 4-way candidate split +
// shfl reduce (first-max-wins tiebreak matches jnp.argmax). 64-thread blocks
// spread the latency-bound phase across all SMs. Streaming loads keep the
// read-once weights/indices from displacing L2 write-buffer capacity.
// ---------------------------------------------------------------------------
__global__ void __launch_bounds__(64) build_sel_kernel(
    const float4* __restrict__ w4, const int* __restrict__ idx) {
    int g = blockIdx.x * 64 + threadIdx.x;           // [0, 16384)
    int lo4 = g >> 2;
    int q   = g & 3;

    float best[4];
    int   bc[4];
    int c0 = q * 16;
    {
        float4 v = __ldcs(w4 + (size_t)c0 * LO4 + lo4);
        best[0] = v.x; best[1] = v.y; best[2] = v.z; best[3] = v.w;
        bc[0] = bc[1] = bc[2] = bc[3] = c0;
    }
#pragma unroll
    for (int j = 1; j < 16; ++j) {
        int c = c0 + j;
        float4 v = __ldcs(w4 + (size_t)c * LO4 + lo4);
        if (v.x > best[0]) { best[0] = v.x; bc[0] = c; }
        if (v.y > best[1]) { best[1] = v.y; bc[1] = c; }
        if (v.z > best[2]) { best[2] = v.z; bc[2] = c; }
        if (v.w > best[3]) { best[3] = v.w; bc[3] = c; }
    }
#pragma unroll
    for (int d = 1; d < 4; d <<= 1) {
#pragma unroll
        for (int k = 0; k < 4; ++k) {
            float ob = __shfl_xor_sync(0xFFFFFFFFu, best[k], d);
            int   oc = __shfl_xor_sync(0xFFFFFFFFu, bc[k], d);
            if (ob > best[k] || (ob == best[k] && oc < bc[k])) {
                best[k] = ob; bc[k] = oc;
            }
        }
    }
    if (q == 0) {
#pragma unroll
        for (int k = 0; k < 4; ++k) {
            int lo = lo4 * 4 + k;
            g_sel[lo] = __ldcs(idx + bc[k] * LO + lo);
        }
    }
    cudaTriggerProgrammaticLaunchCompletion();
}

// ---------------------------------------------------------------------------
// Kernel 2: out[b, lo] = x[b, sel[lo]] for 4 batches per block.
// PDL: stages x rows (sel-independent) while kernel1 drains; sel loads issue
// right after the grid dependency resolves, overlapping the block barrier.
// 4-batch-interleaved LDS.128 gather, 4x4 register transpose, streaming
// coalesced float4 stores.
// ---------------------------------------------------------------------------
__global__ void __launch_bounds__(256) gather_kernel(
    const float* __restrict__ x, float4* __restrict__ out4) {
    __shared__ float4 xq[N_DIM];                 // 8 KB

    int b0    = (blockIdx.x >> 3) * BPB;         // / NCHUNK
    int chunk = blockIdx.x & (NCHUNK - 1);

    // stage x rows first — does not depend on kernel1
    const float* xr0 = x + (size_t)b0 * N_DIM;
#pragma unroll
    for (int r = 0; r < 2; ++r) {
        int n = r * 256 + threadIdx.x;
        float4 v;
        v.x = __ldg(xr0 + n);
        v.y = __ldg(xr0 + N_DIM + n);
        v.z = __ldg(xr0 + 2 * N_DIM + n);
        v.w = __ldg(xr0 + 3 * N_DIM + n);
        xq[n] = v;
    }

    // wait for kernel1's g_sel writes, then issue sel loads immediately
    // (they overlap the staging barrier below)
    cudaGridDependencySynchronize();
    const int4* sel4 = (const int4*)g_sel + chunk * CHUNK4;
    int4 s0 = __ldg(sel4 + threadIdx.x);
    int4 s1 = __ldg(sel4 + 256 + threadIdx.x);
    __syncthreads();

#pragma unroll
    for (int r = 0; r < 2; ++r) {
        int i = r * 256 + threadIdx.x;
        int4 s = (r == 0) ? s0 : s1;
        float4 a = xq[s.x];
        float4 b = xq[s.y];
        float4 c = xq[s.z];
        float4 d = xq[s.w];
        size_t col = (size_t)chunk * CHUNK4 + i;
        __stcs(out4 + (size_t)(b0 + 0) * LO4 + col, make_float4(a.x, b.x, c.x, d.x));
        __stcs(out4 + (size_t)(b0 + 1) * LO4 + col, make_float4(a.y, b.y, c.y, d.y));
        __stcs(out4 + (size_t)(b0 + 2) * LO4 + col, make_float4(a.z, b.z, c.z, d.z));
        __stcs(out4 + (size_t)(b0 + 3) * LO4 + col, make_float4(a.w, b.w, c.w, d.w));
    }
}

extern "C" void kernel_launch(void* const* d_in, const int* in_sizes, int n_in,
                              void* d_out, int out_size) {
    const float* x   = (const float*)d_in[0];
    const float* w   = (const float*)d_in[1];
    const int*   idx = (const int*)d_in[2];
    float4* out = (float4*)d_out;

    build_sel_kernel<<<256, 64>>>((const float4*)w, idx);

    cudaLaunchAttribute attrs[1];
    attrs[0].id = cudaLaunchAttributeProgrammaticStreamSerialization;
    attrs[0].val.programmaticStreamSerializationAllowed = 1;

    cudaLaunchConfig_t cfg = {};
    cfg.gridDim  = dim3((B_DIM / BPB) * NCHUNK);
    cfg.blockDim = dim3(256);
    cfg.dynamicSmemBytes = 0;
    cfg.stream = 0;
    cfg.attrs = attrs;
    cfg.numAttrs = 1;

    cudaLaunchKernelEx(&cfg, gather_kernel, x, out);
}

// round 11
// speedup vs baseline: 1.1657x; 1.1657x over previous
#include <cuda_runtime.h>
#include <cstdint>

#define B_DIM 2048
#define N_DIM 512
#define C_DIM 64
#define L_DIM 2
#define O_DIM 8192
#define LO (L_DIM * O_DIM)      // 16384
#define LO4 (LO / 4)            // 4096

#define BPB 4                   // batches per gather block
#define CHUNK 2048              // lo per gather block
#define CHUNK4 (CHUNK / 4)      // 512 int4 per chunk
#define NCHUNK (LO / CHUNK)     // 8

// Selection table sel[l*O + o] = input-feature index (0..N-1)
__device__ int g_sel[LO];

// ---------------------------------------------------------------------------
// Kernel 1 (R7, proven): argmax over C=64 candidates per (l,o), 4-way
// candidate split + shfl reduce (first-max-wins tiebreak matches jnp.argmax).
// 64-thread blocks spread the latency-bound phase across all SMs.
// Cached __ldg loads (R10's __ldcs regressed badly — high cross-warp reuse).
// ---------------------------------------------------------------------------
__global__ void __launch_bounds__(64) build_sel_kernel(
    const float4* __restrict__ w4, const int* __restrict__ idx) {
    int g = blockIdx.x * 64 + threadIdx.x;           // [0, 16384)
    int lo4 = g >> 2;
    int q   = g & 3;

    float best[4];
    int   bc[4];
    int c0 = q * 16;
    {
        float4 v = __ldg(w4 + (size_t)c0 * LO4 + lo4);
        best[0] = v.x; best[1] = v.y; best[2] = v.z; best[3] = v.w;
        bc[0] = bc[1] = bc[2] = bc[3] = c0;
    }
#pragma unroll
    for (int j = 1; j < 16; ++j) {
        int c = c0 + j;
        float4 v = __ldg(w4 + (size_t)c * LO4 + lo4);
        if (v.x > best[0]) { best[0] = v.x; bc[0] = c; }
        if (v.y > best[1]) { best[1] = v.y; bc[1] = c; }
        if (v.z > best[2]) { best[2] = v.z; bc[2] = c; }
        if (v.w > best[3]) { best[3] = v.w; bc[3] = c; }
    }
#pragma unroll
    for (int d = 1; d < 4; d <<= 1) {
#pragma unroll
        for (int k = 0; k < 4; ++k) {
            float ob = __shfl_xor_sync(0xFFFFFFFFu, best[k], d);
            int   oc = __shfl_xor_sync(0xFFFFFFFFu, bc[k], d);
            if (ob > best[k] || (ob == best[k] && oc < bc[k])) {
                best[k] = ob; bc[k] = oc;
            }
        }
    }
    if (q == 0) {
#pragma unroll
        for (int k = 0; k < 4; ++k) {
            int lo = lo4 * 4 + k;
            g_sel[lo] = __ldg(idx + bc[k] * LO + lo);
        }
    }
    cudaTriggerProgrammaticLaunchCompletion();
}

// ---------------------------------------------------------------------------
// Kernel 2: out[b, lo] = x[b, sel[lo]] for 4 batches per block.
// PDL: stages x rows (sel-independent) while kernel1 drains; sel loads issue
// right after the grid dependency resolves, overlapping the block barrier.
// 4-batch-interleaved LDS.128 gather, 4x4 register transpose, streaming
// coalesced float4 stores.
// ---------------------------------------------------------------------------
__global__ void __launch_bounds__(256) gather_kernel(
    const float* __restrict__ x, float4* __restrict__ out4) {
    __shared__ float4 xq[N_DIM];                 // 8 KB

    int b0    = (blockIdx.x >> 3) * BPB;         // / NCHUNK
    int chunk = blockIdx.x & (NCHUNK - 1);

    // stage x rows first — does not depend on kernel1
    const float* xr0 = x + (size_t)b0 * N_DIM;
#pragma unroll
    for (int r = 0; r < 2; ++r) {
        int n = r * 256 + threadIdx.x;
        float4 v;
        v.x = __ldg(xr0 + n);
        v.y = __ldg(xr0 + N_DIM + n);
        v.z = __ldg(xr0 + 2 * N_DIM + n);
        v.w = __ldg(xr0 + 3 * N_DIM + n);
        xq[n] = v;
    }

    // wait for kernel1's g_sel writes, then issue sel loads immediately
    // (they overlap the staging barrier below)
    cudaGridDependencySynchronize();
    const int4* sel4 = (const int4*)g_sel + chunk * CHUNK4;
    int4 s0 = __ldg(sel4 + threadIdx.x);
    int4 s1 = __ldg(sel4 + 256 + threadIdx.x);
    __syncthreads();

#pragma unroll
    for (int r = 0; r < 2; ++r) {
        int i = r * 256 + threadIdx.x;
        int4 s = (r == 0) ? s0 : s1;
        float4 a = xq[s.x];
        float4 b = xq[s.y];
        float4 c = xq[s.z];
        float4 d = xq[s.w];
        size_t col = (size_t)chunk * CHUNK4 + i;
        __stcs(out4 + (size_t)(b0 + 0) * LO4 + col, make_float4(a.x, b.x, c.x, d.x));
        __stcs(out4 + (size_t)(b0 + 1) * LO4 + col, make_float4(a.y, b.y, c.y, d.y));
        __stcs(out4 + (size_t)(b0 + 2) * LO4 + col, make_float4(a.z, b.z, c.z, d.z));
        __stcs(out4 + (size_t)(b0 + 3) * LO4 + col, make_float4(a.w, b.w, c.w, d.w));
    }
}

extern "C" void kernel_launch(void* const* d_in, const int* in_sizes, int n_in,
                              void* d_out, int out_size) {
    const float* x   = (const float*)d_in[0];
    const float* w   = (const float*)d_in[1];
    const int*   idx = (const int*)d_in[2];
    float4* out = (float4*)d_out;

    build_sel_kernel<<<256, 64>>>((const float4*)w, idx);

    cudaLaunchAttribute attrs[1];
    attrs[0].id = cudaLaunchAttributeProgrammaticStreamSerialization;
    attrs[0].val.programmaticStreamSerializationAllowed = 1;

    cudaLaunchConfig_t cfg = {};
    cfg.gridDim  = dim3((B_DIM / BPB) * NCHUNK);
    cfg.blockDim = dim3(256);
    cfg.dynamicSmemBytes = 0;
    cfg.stream = 0;
    cfg.attrs = attrs;
    cfg.numAttrs = 1;

    cudaLaunchKernelEx(&cfg, gather_kernel, x, out);
}

// round 12
// speedup vs baseline: 1.2373x; 1.0614x over previous
#include <cuda_runtime.h>
#include <cstdint>

#define B_DIM 2048
#define N_DIM 512
#define C_DIM 64
#define L_DIM 2
#define O_DIM 8192
#define LO (L_DIM * O_DIM)      // 16384
#define LO4 (LO / 4)            // 4096

#define TPB 512                 // gather threads per block
#define BPB 8                   // batches per gather block
#define CHUNK 4096              // lo per gather block
#define CHUNK4 (CHUNK / 4)      // 1024 int4 per chunk
#define NCHUNK (LO / CHUNK)     // 4
#define GITER (CHUNK4 / TPB)    // 2

// Selection table sel[l*O + o] = input-feature index (0..N-1)
__device__ int g_sel[LO];

// ---------------------------------------------------------------------------
// Kernel 1 (proven R7): argmax over C=64 candidates per (l,o), 4-way
// candidate split + shfl reduce (first-max-wins tiebreak matches jnp.argmax).
// ---------------------------------------------------------------------------
__global__ void __launch_bounds__(64) build_sel_kernel(
    const float4* __restrict__ w4, const int* __restrict__ idx) {
    int g = blockIdx.x * 64 + threadIdx.x;           // [0, 16384)
    int lo4 = g >> 2;
    int q   = g & 3;

    float best[4];
    int   bc[4];
    int c0 = q * 16;
    {
        float4 v = __ldg(w4 + (size_t)c0 * LO4 + lo4);
        best[0] = v.x; best[1] = v.y; best[2] = v.z; best[3] = v.w;
        bc[0] = bc[1] = bc[2] = bc[3] = c0;
    }
#pragma unroll
    for (int j = 1; j < 16; ++j) {
        int c = c0 + j;
        float4 v = __ldg(w4 + (size_t)c * LO4 + lo4);
        if (v.x > best[0]) { best[0] = v.x; bc[0] = c; }
        if (v.y > best[1]) { best[1] = v.y; bc[1] = c; }
        if (v.z > best[2]) { best[2] = v.z; bc[2] = c; }
        if (v.w > best[3]) { best[3] = v.w; bc[3] = c; }
    }
#pragma unroll
    for (int d = 1; d < 4; d <<= 1) {
#pragma unroll
        for (int k = 0; k < 4; ++k) {
            float ob = __shfl_xor_sync(0xFFFFFFFFu, best[k], d);
            int   oc = __shfl_xor_sync(0xFFFFFFFFu, bc[k], d);
            if (ob > best[k] || (ob == best[k] && oc < bc[k])) {
                best[k] = ob; bc[k] = oc;
            }
        }
    }
    if (q == 0) {
#pragma unroll
        for (int k = 0; k < 4; ++k) {
            int lo = lo4 * 4 + k;
            g_sel[lo] = __ldg(idx + bc[k] * LO + lo);
        }
    }
    cudaTriggerProgrammaticLaunchCompletion();
}

// ---------------------------------------------------------------------------
// Kernel 2: out[b, lo] = x[b, sel[lo]] for 8 batches per block (two 4-batch
// interleaved smem tiles). One int4 sel read serves 32 output elements;
// staging redundancy is NCHUNK=4 (half of R7). PDL overlap with kernel1.
// ---------------------------------------------------------------------------
__global__ void __launch_bounds__(TPB) gather_kernel(
    const float* __restrict__ x, float4* __restrict__ out4) {
    __shared__ float4 xq0[N_DIM];                // batches b0..b3, 8 KB
    __shared__ float4 xq1[N_DIM];                // batches b4..b7, 8 KB

    int b0    = (blockIdx.x >> 2) * BPB;         // / NCHUNK
    int chunk = blockIdx.x & (NCHUNK - 1);

    // stage 8 x rows (sel-independent) — 512 threads cover 512 columns
    const float* xr = x + (size_t)b0 * N_DIM;
    if (threadIdx.x < N_DIM) {
        int n = threadIdx.x;
        float4 v0, v1;
        v0.x = __ldg(xr + n);
        v0.y = __ldg(xr + N_DIM + n);
        v0.z = __ldg(xr + 2 * N_DIM + n);
        v0.w = __ldg(xr + 3 * N_DIM + n);
        v1.x = __ldg(xr + 4 * N_DIM + n);
        v1.y = __ldg(xr + 5 * N_DIM + n);
        v1.z = __ldg(xr + 6 * N_DIM + n);
        v1.w = __ldg(xr + 7 * N_DIM + n);
        xq0[n] = v0;
        xq1[n] = v1;
    }

    // wait for kernel1's g_sel writes; issue sel loads before the barrier
    cudaGridDependencySynchronize();
    const int4* sel4 = (const int4*)g_sel + chunk * CHUNK4;
    int4 s0 = __ldg(sel4 + threadIdx.x);
    int4 s1 = __ldg(sel4 + TPB + threadIdx.x);
    __syncthreads();

#pragma unroll
    for (int r = 0; r < GITER; ++r) {
        int i = r * TPB + threadIdx.x;
        int4 s = (r == 0) ? s0 : s1;
        float4 a0 = xq0[s.x], a1 = xq0[s.y], a2 = xq0[s.z], a3 = xq0[s.w];
        float4 c0 = xq1[s.x], c1 = xq1[s.y], c2 = xq1[s.z], c3 = xq1[s.w];
        size_t col = (size_t)chunk * CHUNK4 + i;
        __stcs(out4 + (size_t)(b0 + 0) * LO4 + col, make_float4(a0.x, a1.x, a2.x, a3.x));
        __stcs(out4 + (size_t)(b0 + 1) * LO4 + col, make_float4(a0.y, a1.y, a2.y, a3.y));
        __stcs(out4 + (size_t)(b0 + 2) * LO4 + col, make_float4(a0.z, a1.z, a2.z, a3.z));
        __stcs(out4 + (size_t)(b0 + 3) * LO4 + col, make_float4(a0.w, a1.w, a2.w, a3.w));
        __stcs(out4 + (size_t)(b0 + 4) * LO4 + col, make_float4(c0.x, c1.x, c2.x, c3.x));
        __stcs(out4 + (size_t)(b0 + 5) * LO4 + col, make_float4(c0.y, c1.y, c2.y, c3.y));
        __stcs(out4 + (size_t)(b0 + 6) * LO4 + col, make_float4(c0.z, c1.z, c2.z, c3.z));
        __stcs(out4 + (size_t)(b0 + 7) * LO4 + col, make_float4(c0.w, c1.w, c2.w, c3.w));
    }
}

extern "C" void kernel_launch(void* const* d_in, const int* in_sizes, int n_in,
                              void* d_out, int out_size) {
    const float* x   = (const float*)d_in[0];
    const float* w   = (const float*)d_in[1];
    const int*   idx = (const int*)d_in[2];
    float4* out = (float4*)d_out;

    build_sel_kernel<<<256, 64>>>((const float4*)w, idx);

    cudaLaunchAttribute attrs[1];
    attrs[0].id = cudaLaunchAttributeProgrammaticStreamSerialization;
    attrs[0].val.programmaticStreamSerializationAllowed = 1;

    cudaLaunchConfig_t cfg = {};
    cfg.gridDim  = dim3((B_DIM / BPB) * NCHUNK);   // 1024
    cfg.blockDim = dim3(TPB);
    cfg.dynamicSmemBytes = 0;
    cfg.stream = 0;
    cfg.attrs = attrs;
    cfg.numAttrs = 1;

    cudaLaunchKernelEx(&cfg, gather_kernel, x, out);
}